// round 6
// baseline (speedup 1.0000x reference)
#include <cuda_runtime.h>
#include <cstdint>
#include <cstddef>

// ============================================================================
// LSTM (B=8192, H=512, T=32, F=96) on sm_100 (plain target!) via
// mma.sync.m16n8k8 TF32 tensor cores (tcgen05 unavailable: harness compiles
// through compute_100 PTX, which rejects all 'a'-suffix features).
//
//   prep_x    : inputs[B,3,32,32] -> g_xT[t][b][96]  (tf32-rounded)
//   prep_misc : h0 -> g_h[0] (tf32), c0 -> g_c, W tf32 copies, bias = bih+bhh
//   step x32  : gates = [h | x_t] @ Wcat^T  + fused LSTM pointwise epilogue
//   final     : out = h_31 @ W_out^T + b_out
//
// Step kernel: CTA tile M=256 x N=128 (N = 4 gates x 32 hidden units so the
// epilogue is CTA-local), 512 threads = 16 warps in a 4x4 grid, warp tile
// 64x32. K=608 in 19 chunks of 32 fp32 (128B rows), 3-stage cp.async
// pipeline. Fragments use a k-permutation (cols {2q,2q+1} instead of
// {q,q+4}) applied identically to A and B so each fragment piece is one
// ld.shared.v2; smem uses a 16B-chunk XOR swizzle (chunk ^= row&7).
// Epilogue: accums -> smem (pitch 132 floats, conflict-free) -> recombine
// gates per (row, unit) -> c/h update, float4 stores.
// ============================================================================

#define DEVI __device__ __forceinline__

#define BATCH   8192
#define HID     512
#define G4      2048
#define TSTEPS  32
#define INFEAT  96
#define NCHUNK  19
#define THREADS 512

#define STAGE_A   32768              // 256 rows x 128B
#define STAGE_B   16384              // 128 rows x 128B
#define STAGE     (STAGE_A + STAGE_B)        // 49152
#define BIAS_OFF  (3 * STAGE)                // 147456
#define SMEM_NEED (BIAS_OFF + 512)           // 147968
#define SMEM_ALLOC (SMEM_NEED + 256)         // align slack
#define CPITCH    132                 // epilogue smem pitch in floats

// ------------------------- device scratch (no allocs) -----------------------
__device__ float g_h[2][BATCH * HID];
__device__ float g_c[BATCH * HID];
__device__ float g_bias[G4];
__device__ float g_Whh[G4 * HID];
__device__ float g_Wih[G4 * INFEAT];
__device__ float g_xT[TSTEPS * BATCH * INFEAT];

// ------------------------------ helpers -------------------------------------
DEVI uint32_t smem_u32(const void* p) {
    uint32_t a;
    asm("{ .reg .u64 t; cvta.to.shared.u64 t, %1; cvt.u32.u64 %0, t; }" : "=r"(a) : "l"(p));
    return a;
}
DEVI float to_tf32(float x) {
    uint32_t o;
    asm("cvt.rna.tf32.f32 %0, %1;" : "=r"(o) : "f"(x));
    return __uint_as_float(o);
}
DEVI float ex2f(float x) { float y; asm("ex2.approx.f32 %0, %1;" : "=f"(y) : "f"(x)); return y; }
DEVI float rcpf(float x) { float y; asm("rcp.approx.f32 %0, %1;" : "=f"(y) : "f"(x)); return y; }
DEVI float sigm(float x) { return rcpf(1.0f + ex2f(x * -1.44269504088896f)); }
DEVI float tanh_(float x) { return fmaf(2.0f, sigm(x + x), -1.0f); }

DEVI void cp16(uint32_t sdst, const void* gsrc) {
    asm volatile("cp.async.cg.shared.global [%0], [%1], 16;" :: "r"(sdst), "l"(gsrc) : "memory");
}
DEVI void mma_tf32(float* c, uint32_t a0, uint32_t a1, uint32_t a2, uint32_t a3,
                   uint32_t b0, uint32_t b1) {
    asm volatile(
        "mma.sync.aligned.m16n8k8.row.col.f32.tf32.tf32.f32 "
        "{%0,%1,%2,%3}, {%4,%5,%6,%7}, {%8,%9}, {%0,%1,%2,%3};"
        : "+f"(c[0]), "+f"(c[1]), "+f"(c[2]), "+f"(c[3])
        : "r"(a0), "r"(a1), "r"(a2), "r"(a3), "r"(b0), "r"(b1));
}

// ------------------------------ prep kernels --------------------------------
// inputs[b, ch, t, w] -> g_xT[(t*BATCH + b)*96 + w*3 + ch], tf32-rounded
__global__ void prep_x_kernel(const float* __restrict__ in) {
    int idx = blockIdx.x * blockDim.x + threadIdx.x;
    if (idx >= BATCH * 3 * 32 * 32) return;
    int w  = idx & 31;
    int t  = (idx >> 5) & 31;
    int c3 = idx >> 10;            // b*3 + ch
    int ch = c3 % 3;
    int b  = c3 / 3;
    g_xT[((size_t)t * BATCH + b) * INFEAT + w * 3 + ch] = to_tf32(in[idx]);
}

__global__ void prep_misc_kernel(const float* __restrict__ h0, const float* __restrict__ c0,
                                 const float* __restrict__ Wih, const float* __restrict__ Whh,
                                 const float* __restrict__ bih, const float* __restrict__ bhh) {
    int i = blockIdx.x * blockDim.x + threadIdx.x;
    if (i < BATCH * HID) {
        g_h[0][i] = to_tf32(h0[i]);
        g_c[i]    = c0[i];
    }
    if (i < G4 * HID)    g_Whh[i] = to_tf32(Whh[i]);
    if (i < G4 * INFEAT) g_Wih[i] = to_tf32(Wih[i]);
    if (i < G4)          g_bias[i] = bih[i] + bhh[i];
}

// ------------------------- step kernel chunk loader -------------------------
// A tile: 256 rows x 32 fp32 from [h | x_t]; B tile: 128 rows (n: gate=n&3,
// unit=nh+(n>>2)) x 32 fp32 from [Whh | Wih]. 16B chunks, swizzle c^(row&7).
DEVI void load_chunk(int kc, uint32_t stA, uint32_t stB, int tid, int brow0, int nh,
                     const float* __restrict__ hin, const float* __restrict__ xT) {
    const float* abase; int apitch;
    if (kc < 16) { abase = hin + (size_t)brow0 * HID + kc * 32;            apitch = HID; }
    else         { abase = xT  + (size_t)brow0 * INFEAT + (kc - 16) * 32;  apitch = INFEAT; }
    #pragma unroll
    for (int u = 0; u < 4; u++) {
        int ch = tid + u * THREADS;          // 0..2047
        int r = ch >> 3, cc = ch & 7;
        uint32_t dst = stA + r * 128 + ((cc ^ (r & 7)) << 4);
        cp16(dst, abase + (size_t)r * apitch + cc * 4);
    }
    const float* wbase; int wpitch, kk;
    if (kc < 16) { wbase = g_Whh; wpitch = HID;    kk = kc * 32; }
    else         { wbase = g_Wih; wpitch = INFEAT; kk = (kc - 16) * 32; }
    #pragma unroll
    for (int u = 0; u < 2; u++) {
        int ch = tid + u * THREADS;          // 0..1023
        int r = ch >> 3, cc = ch & 7;
        int wrow = (r & 3) * HID + nh + (r >> 2);     // gate*512 + unit
        uint32_t dst = stB + r * 128 + ((cc ^ (r & 7)) << 4);
        cp16(dst, wbase + (size_t)wrow * wpitch + kk + cc * 4);
    }
    asm volatile("cp.async.commit_group;" ::: "memory");
}

// ------------------------------- step kernel --------------------------------
__global__ void __launch_bounds__(THREADS, 1) step_kernel(int t) {
    extern __shared__ char dsm[];
    uint32_t sb = smem_u32(dsm);
    sb = (sb + 127u) & ~127u;

    const int tid  = threadIdx.x;
    const int warp = tid >> 5, lane = tid & 31;
    const int wm = warp >> 2, wn = warp & 3;     // 4x4 warp grid
    const int g  = lane >> 2, q = lane & 3;
    const int nh    = blockIdx.y * 32;           // hidden-unit slice base
    const int brow0 = blockIdx.x * 256;          // batch-row base

    const float* __restrict__ hin  = g_h[t & 1];
    float*       __restrict__ hout = g_h[(t + 1) & 1];
    const float* __restrict__ xT   = g_xT + (size_t)t * BATCH * INFEAT;

    // bias slice -> smem[BIAS_OFF..+512): col n -> g_bias[(n&3)*512 + nh + (n>>2)]
    if (tid < 128) {
        float bv = g_bias[(tid & 3) * HID + nh + (tid >> 2)];
        asm volatile("st.shared.f32 [%0], %1;" :: "r"(sb + BIAS_OFF + tid * 4), "f"(bv));
    }

    load_chunk(0, sb,             sb + STAGE_A,             tid, brow0, nh, hin, xT);
    load_chunk(1, sb + STAGE,     sb + STAGE + STAGE_A,     tid, brow0, nh, hin, xT);

    float acc[4][4][4] = {};

    for (int kc = 0; kc < NCHUNK; kc++) {
        if (kc < NCHUNK - 1) asm volatile("cp.async.wait_group 1;" ::: "memory");
        else                 asm volatile("cp.async.wait_group 0;" ::: "memory");
        __syncthreads();
        if (kc + 2 < NCHUNK) {
            int s = (kc + 2) % 3;
            load_chunk(kc + 2, sb + s * STAGE, sb + s * STAGE + STAGE_A, tid, brow0, nh, hin, xT);
        }
        const uint32_t stA = sb + (kc % 3) * STAGE;
        const uint32_t stB = stA + STAGE_A;

        #pragma unroll
        for (int kb = 0; kb < 4; kb++) {
            // swizzled byte offset of the v2 pair {2q, 2q+1} within a row:
            // chunk = (2kb + q>>1) ^ (row&7 = g), half = 8*(q&1)
            const uint32_t sw = ((uint32_t)((2 * kb + (q >> 1)) ^ g) << 4) + ((q & 1) << 3);
            uint32_t a0[4], a1[4], a2[4], a3[4];
            #pragma unroll
            for (int m = 0; m < 4; m++) {
                uint32_t ra = stA + (uint32_t)(wm * 64 + m * 16 + g) * 128 + sw;
                asm volatile("ld.shared.v2.u32 {%0,%1}, [%2];"
                             : "=r"(a0[m]), "=r"(a2[m]) : "r"(ra));
                asm volatile("ld.shared.v2.u32 {%0,%1}, [%2];"
                             : "=r"(a1[m]), "=r"(a3[m]) : "r"(ra + 8 * 128));
            }
            uint32_t b0[4], b1[4];
            #pragma unroll
            for (int n = 0; n < 4; n++) {
                uint32_t rb = stB + (uint32_t)(wn * 32 + n * 8 + g) * 128 + sw;
                asm volatile("ld.shared.v2.u32 {%0,%1}, [%2];"
                             : "=r"(b0[n]), "=r"(b1[n]) : "r"(rb));
            }
            #pragma unroll
            for (int m = 0; m < 4; m++)
                #pragma unroll
                for (int n = 0; n < 4; n++)
                    mma_tf32(acc[m][n], a0[m], a1[m], a2[m], a3[m], b0[n], b1[n]);
        }
    }

    // ------------------- epilogue: exchange gates via smem -------------------
    __syncthreads();                 // all compute done; stage smem reusable
    #pragma unroll
    for (int m = 0; m < 4; m++) {
        const int r0 = wm * 64 + m * 16 + g;
        #pragma unroll
        for (int n = 0; n < 4; n++) {
            const int col = wn * 32 + n * 8 + 2 * q;
            uint32_t ad = sb + (uint32_t)(r0 * CPITCH + col) * 4;
            asm volatile("st.shared.v2.f32 [%0], {%1,%2};"
                         :: "r"(ad), "f"(acc[m][n][0]), "f"(acc[m][n][1]) : "memory");
            asm volatile("st.shared.v2.f32 [%0], {%1,%2};"
                         :: "r"(ad + 8 * CPITCH * 4), "f"(acc[m][n][2]), "f"(acc[m][n][3]) : "memory");
        }
    }
    __syncthreads();

    #pragma unroll
    for (int it = 0; it < 2; it++) {
        const int task = tid + it * THREADS;     // 0..1023
        const int row  = task >> 2;              // 0..255
        const int ug   = task & 3;               // unit-group (8 units)
        const int b    = brow0 + row;
        const uint32_t rb = sb + (uint32_t)(row * CPITCH + ug * 32) * 4;
        const uint32_t bb = sb + BIAS_OFF + (uint32_t)(ug * 32) * 4;

        float* cptr = g_c  + (size_t)b * HID + nh + ug * 8;
        float* hptr = hout + (size_t)b * HID + nh + ug * 8;
        float4 cA = *(const float4*)(cptr);
        float4 cB = *(const float4*)(cptr + 4);
        float cold[8] = {cA.x, cA.y, cA.z, cA.w, cB.x, cB.y, cB.z, cB.w};
        float cn[8], hn[8];

        #pragma unroll
        for (int k = 0; k < 8; k++) {
            float vx, vy, vz, vw, bx, by, bz, bw;
            asm volatile("ld.shared.v4.f32 {%0,%1,%2,%3}, [%4];"
                         : "=f"(vx), "=f"(vy), "=f"(vz), "=f"(vw) : "r"(rb + k * 16));
            asm volatile("ld.shared.v4.f32 {%0,%1,%2,%3}, [%4];"
                         : "=f"(bx), "=f"(by), "=f"(bz), "=f"(bw) : "r"(bb + k * 16));
            float iv = sigm(vx + bx);
            float fv = sigm(vy + by);
            float gv = tanh_(vz + bz);
            float ov = sigm(vw + bw);
            cn[k] = fmaf(fv, cold[k], iv * gv);
            hn[k] = to_tf32(ov * tanh_(cn[k]));   // tf32-round h for next MMA
        }
        *(float4*)(cptr)     = make_float4(cn[0], cn[1], cn[2], cn[3]);
        *(float4*)(cptr + 4) = make_float4(cn[4], cn[5], cn[6], cn[7]);
        *(float4*)(hptr)     = make_float4(hn[0], hn[1], hn[2], hn[3]);
        *(float4*)(hptr + 4) = make_float4(hn[4], hn[5], hn[6], hn[7]);
    }
}

// ------------------------------- final kernel -------------------------------
__global__ void final_kernel(const float* __restrict__ Wout, const float* __restrict__ bout,
                             float* __restrict__ out) {
    int idx = blockIdx.x * blockDim.x + threadIdx.x;   // 81920
    if (idx >= BATCH * 10) return;
    int b = idx / 10, cls = idx % 10;
    const float* h  = g_h[0] + (size_t)b * HID;        // step 31 wrote g_h[0]
    const float* wv = Wout + (size_t)cls * HID;
    float acc = 0.f;
    #pragma unroll 4
    for (int i = 0; i < HID; i += 4) {
        float4 hv = *(const float4*)(h + i);
        float4 wf = *(const float4*)(wv + i);
        acc = fmaf(hv.x, wf.x, acc);
        acc = fmaf(hv.y, wf.y, acc);
        acc = fmaf(hv.z, wf.z, acc);
        acc = fmaf(hv.w, wf.w, acc);
    }
    out[idx] = acc + bout[cls];
}

// --------------------------------- launch -----------------------------------
extern "C" void kernel_launch(void* const* d_in, const int* in_sizes, int n_in,
                              void* d_out, int out_size) {
    const float* inputs = (const float*)d_in[0];
    const float* h0     = (const float*)d_in[1];
    const float* c0     = (const float*)d_in[2];
    const float* W_ih   = (const float*)d_in[3];
    const float* W_hh   = (const float*)d_in[4];
    const float* b_ih   = (const float*)d_in[5];
    const float* b_hh   = (const float*)d_in[6];
    const float* W_out  = (const float*)d_in[7];
    const float* b_out  = (const float*)d_in[8];
    float* out = (float*)d_out;
    (void)in_sizes; (void)n_in; (void)out_size;

    cudaFuncSetAttribute(step_kernel, cudaFuncAttributeMaxDynamicSharedMemorySize, SMEM_ALLOC);

    prep_x_kernel<<<(BATCH * 3 * 32 * 32 + 255) / 256, 256>>>(inputs);
    prep_misc_kernel<<<(BATCH * HID + 255) / 256, 256>>>(h0, c0, W_ih, W_hh, b_ih, b_hh);

    dim3 grid(BATCH / 256, HID / 32);   // (32, 16) = 512 CTAs
    for (int t = 0; t < TSTEPS; t++)
        step_kernel<<<grid, THREADS, SMEM_ALLOC>>>(t);

    final_kernel<<<(BATCH * 10 + 255) / 256, 256>>>(W_out, b_out, out);
}

// round 7
// speedup vs baseline: 1.1966x; 1.1966x over previous
#include <cuda_runtime.h>
#include <cstdint>
#include <cstddef>

// ============================================================================
// LSTM (B=8192, H=512, T=32, F=96) on sm_100 via mma.sync.m16n8k8 TF32.
//
// R7 change vs R6 (passed, 6243us, issue=30%, occ=25%, 1 CTA/SM):
//   CTA halved to M=128 x N=128, 256 threads (8 warps, 2x4), smem ~99KB
//   -> __launch_bounds__(256,2): 2 CTAs/SM so barrier/wait_group stalls of
//   one CTA are covered by the other. Warp tile (64x32), fragment math,
//   swizzle, pipeline depth (3 stages), epilogue all unchanged.
// ============================================================================

#define DEVI __device__ __forceinline__

#define BATCH   8192
#define HID     512
#define G4      2048
#define TSTEPS  32
#define INFEAT  96
#define NCHUNK  19
#define THREADS 256

#define STAGE_A   16384              // 128 rows x 128B
#define STAGE_B   16384              // 128 rows x 128B
#define STAGE     (STAGE_A + STAGE_B)        // 32768
#define BIAS_OFF  (3 * STAGE)                // 98304
#define SMEM_NEED (BIAS_OFF + 512)           // 98816
#define SMEM_ALLOC (SMEM_NEED + 256)         // align slack
#define CPITCH    132                 // epilogue smem pitch in floats (128x132x4=67584 fits)

// ------------------------- device scratch (no allocs) -----------------------
__device__ float g_h[2][BATCH * HID];
__device__ float g_c[BATCH * HID];
__device__ float g_bias[G4];
__device__ float g_Whh[G4 * HID];
__device__ float g_Wih[G4 * INFEAT];
__device__ float g_xT[TSTEPS * BATCH * INFEAT];

// ------------------------------ helpers -------------------------------------
DEVI uint32_t smem_u32(const void* p) {
    uint32_t a;
    asm("{ .reg .u64 t; cvta.to.shared.u64 t, %1; cvt.u32.u64 %0, t; }" : "=r"(a) : "l"(p));
    return a;
}
DEVI float to_tf32(float x) {
    uint32_t o;
    asm("cvt.rna.tf32.f32 %0, %1;" : "=r"(o) : "f"(x));
    return __uint_as_float(o);
}
DEVI float ex2f(float x) { float y; asm("ex2.approx.f32 %0, %1;" : "=f"(y) : "f"(x)); return y; }
DEVI float rcpf(float x) { float y; asm("rcp.approx.f32 %0, %1;" : "=f"(y) : "f"(x)); return y; }
DEVI float sigm(float x) { return rcpf(1.0f + ex2f(x * -1.44269504088896f)); }
DEVI float tanh_(float x) { return fmaf(2.0f, sigm(x + x), -1.0f); }

DEVI void cp16(uint32_t sdst, const void* gsrc) {
    asm volatile("cp.async.cg.shared.global [%0], [%1], 16;" :: "r"(sdst), "l"(gsrc) : "memory");
}
DEVI void mma_tf32(float* c, uint32_t a0, uint32_t a1, uint32_t a2, uint32_t a3,
                   uint32_t b0, uint32_t b1) {
    asm volatile(
        "mma.sync.aligned.m16n8k8.row.col.f32.tf32.tf32.f32 "
        "{%0,%1,%2,%3}, {%4,%5,%6,%7}, {%8,%9}, {%0,%1,%2,%3};"
        : "+f"(c[0]), "+f"(c[1]), "+f"(c[2]), "+f"(c[3])
        : "r"(a0), "r"(a1), "r"(a2), "r"(a3), "r"(b0), "r"(b1));
}

// ------------------------------ prep kernels --------------------------------
// inputs[b, ch, t, w] -> g_xT[(t*BATCH + b)*96 + w*3 + ch], tf32-rounded
__global__ void prep_x_kernel(const float* __restrict__ in) {
    int idx = blockIdx.x * blockDim.x + threadIdx.x;
    if (idx >= BATCH * 3 * 32 * 32) return;
    int w  = idx & 31;
    int t  = (idx >> 5) & 31;
    int c3 = idx >> 10;            // b*3 + ch
    int ch = c3 % 3;
    int b  = c3 / 3;
    g_xT[((size_t)t * BATCH + b) * INFEAT + w * 3 + ch] = to_tf32(in[idx]);
}

__global__ void prep_misc_kernel(const float* __restrict__ h0, const float* __restrict__ c0,
                                 const float* __restrict__ Wih, const float* __restrict__ Whh,
                                 const float* __restrict__ bih, const float* __restrict__ bhh) {
    int i = blockIdx.x * blockDim.x + threadIdx.x;
    if (i < BATCH * HID) {
        g_h[0][i] = to_tf32(h0[i]);
        g_c[i]    = c0[i];
    }
    if (i < G4 * HID)    g_Whh[i] = to_tf32(Whh[i]);
    if (i < G4 * INFEAT) g_Wih[i] = to_tf32(Wih[i]);
    if (i < G4)          g_bias[i] = bih[i] + bhh[i];
}

// ------------------------- step kernel chunk loader -------------------------
// A tile: 128 rows x 32 fp32 from [h | x_t]; B tile: 128 rows (n: gate=n&3,
// unit=nh+(n>>2)) x 32 fp32 from [Whh | Wih]. 16B chunks, swizzle c^(row&7).
DEVI void load_chunk(int kc, uint32_t stA, uint32_t stB, int tid, int brow0, int nh,
                     const float* __restrict__ hin, const float* __restrict__ xT) {
    const float* abase; int apitch;
    if (kc < 16) { abase = hin + (size_t)brow0 * HID + kc * 32;            apitch = HID; }
    else         { abase = xT  + (size_t)brow0 * INFEAT + (kc - 16) * 32;  apitch = INFEAT; }
    #pragma unroll
    for (int u = 0; u < 4; u++) {
        int ch = tid + u * THREADS;          // 0..1023
        int r = ch >> 3, cc = ch & 7;
        uint32_t dst = stA + r * 128 + ((cc ^ (r & 7)) << 4);
        cp16(dst, abase + (size_t)r * apitch + cc * 4);
    }
    const float* wbase; int wpitch, kk;
    if (kc < 16) { wbase = g_Whh; wpitch = HID;    kk = kc * 32; }
    else         { wbase = g_Wih; wpitch = INFEAT; kk = (kc - 16) * 32; }
    #pragma unroll
    for (int u = 0; u < 4; u++) {
        int ch = tid + u * THREADS;          // 0..1023
        int r = ch >> 3, cc = ch & 7;
        int wrow = (r & 3) * HID + nh + (r >> 2);     // gate*512 + unit
        uint32_t dst = stB + r * 128 + ((cc ^ (r & 7)) << 4);
        cp16(dst, wbase + (size_t)wrow * wpitch + kk + cc * 4);
    }
    asm volatile("cp.async.commit_group;" ::: "memory");
}

// ------------------------------- step kernel --------------------------------
__global__ void __launch_bounds__(THREADS, 2) step_kernel(int t) {
    extern __shared__ char dsm[];
    uint32_t sb = smem_u32(dsm);
    sb = (sb + 127u) & ~127u;

    const int tid  = threadIdx.x;
    const int warp = tid >> 5, lane = tid & 31;
    const int wm = warp >> 2, wn = warp & 3;     // 2x4 warp grid
    const int g  = lane >> 2, q = lane & 3;
    const int nh    = blockIdx.y * 32;           // hidden-unit slice base
    const int brow0 = blockIdx.x * 128;          // batch-row base

    const float* __restrict__ hin  = g_h[t & 1];
    float*       __restrict__ hout = g_h[(t + 1) & 1];
    const float* __restrict__ xT   = g_xT + (size_t)t * BATCH * INFEAT;

    // bias slice -> smem[BIAS_OFF..+512): col n -> g_bias[(n&3)*512 + nh + (n>>2)]
    if (tid < 128) {
        float bv = g_bias[(tid & 3) * HID + nh + (tid >> 2)];
        asm volatile("st.shared.f32 [%0], %1;" :: "r"(sb + BIAS_OFF + tid * 4), "f"(bv));
    }

    load_chunk(0, sb,             sb + STAGE_A,             tid, brow0, nh, hin, xT);
    load_chunk(1, sb + STAGE,     sb + STAGE + STAGE_A,     tid, brow0, nh, hin, xT);

    float acc[4][4][4] = {};

    for (int kc = 0; kc < NCHUNK; kc++) {
        if (kc < NCHUNK - 1) asm volatile("cp.async.wait_group 1;" ::: "memory");
        else                 asm volatile("cp.async.wait_group 0;" ::: "memory");
        __syncthreads();
        if (kc + 2 < NCHUNK) {
            int s = (kc + 2) % 3;
            load_chunk(kc + 2, sb + s * STAGE, sb + s * STAGE + STAGE_A, tid, brow0, nh, hin, xT);
        }
        const uint32_t stA = sb + (kc % 3) * STAGE;
        const uint32_t stB = stA + STAGE_A;

        #pragma unroll
        for (int kb = 0; kb < 4; kb++) {
            // swizzled byte offset of the v2 pair {2q, 2q+1} within a row:
            // chunk = (2kb + q>>1) ^ (row&7 = g), half = 8*(q&1)
            const uint32_t sw = ((uint32_t)((2 * kb + (q >> 1)) ^ g) << 4) + ((q & 1) << 3);
            uint32_t a0[4], a1[4], a2[4], a3[4];
            #pragma unroll
            for (int m = 0; m < 4; m++) {
                uint32_t ra = stA + (uint32_t)(wm * 64 + m * 16 + g) * 128 + sw;
                asm volatile("ld.shared.v2.u32 {%0,%1}, [%2];"
                             : "=r"(a0[m]), "=r"(a2[m]) : "r"(ra));
                asm volatile("ld.shared.v2.u32 {%0,%1}, [%2];"
                             : "=r"(a1[m]), "=r"(a3[m]) : "r"(ra + 8 * 128));
            }
            uint32_t b0[4], b1[4];
            #pragma unroll
            for (int n = 0; n < 4; n++) {
                uint32_t rb = stB + (uint32_t)(wn * 32 + n * 8 + g) * 128 + sw;
                asm volatile("ld.shared.v2.u32 {%0,%1}, [%2];"
                             : "=r"(b0[n]), "=r"(b1[n]) : "r"(rb));
            }
            #pragma unroll
            for (int m = 0; m < 4; m++)
                #pragma unroll
                for (int n = 0; n < 4; n++)
                    mma_tf32(acc[m][n], a0[m], a1[m], a2[m], a3[m], b0[n], b1[n]);
        }
    }

    // ------------------- epilogue: exchange gates via smem -------------------
    __syncthreads();                 // all compute done; stage smem reusable
    #pragma unroll
    for (int m = 0; m < 4; m++) {
        const int r0 = wm * 64 + m * 16 + g;
        #pragma unroll
        for (int n = 0; n < 4; n++) {
            const int col = wn * 32 + n * 8 + 2 * q;
            uint32_t ad = sb + (uint32_t)(r0 * CPITCH + col) * 4;
            asm volatile("st.shared.v2.f32 [%0], {%1,%2};"
                         :: "r"(ad), "f"(acc[m][n][0]), "f"(acc[m][n][1]) : "memory");
            asm volatile("st.shared.v2.f32 [%0], {%1,%2};"
                         :: "r"(ad + 8 * CPITCH * 4), "f"(acc[m][n][2]), "f"(acc[m][n][3]) : "memory");
        }
    }
    __syncthreads();

    #pragma unroll
    for (int it = 0; it < 2; it++) {
        const int task = tid + it * THREADS;     // 0..511
        const int row  = task >> 2;              // 0..127
        const int ug   = task & 3;               // unit-group (8 units)
        const int b    = brow0 + row;
        const uint32_t rb = sb + (uint32_t)(row * CPITCH + ug * 32) * 4;
        const uint32_t bb = sb + BIAS_OFF + (uint32_t)(ug * 32) * 4;

        float* cptr = g_c  + (size_t)b * HID + nh + ug * 8;
        float* hptr = hout + (size_t)b * HID + nh + ug * 8;
        float4 cA = *(const float4*)(cptr);
        float4 cB = *(const float4*)(cptr + 4);
        float cold[8] = {cA.x, cA.y, cA.z, cA.w, cB.x, cB.y, cB.z, cB.w};
        float cn[8], hn[8];

        #pragma unroll
        for (int k = 0; k < 8; k++) {
            float vx, vy, vz, vw, bx, by, bz, bw;
            asm volatile("ld.shared.v4.f32 {%0,%1,%2,%3}, [%4];"
                         : "=f"(vx), "=f"(vy), "=f"(vz), "=f"(vw) : "r"(rb + k * 16));
            asm volatile("ld.shared.v4.f32 {%0,%1,%2,%3}, [%4];"
                         : "=f"(bx), "=f"(by), "=f"(bz), "=f"(bw) : "r"(bb + k * 16));
            float iv = sigm(vx + bx);
            float fv = sigm(vy + by);
            float gv = tanh_(vz + bz);
            float ov = sigm(vw + bw);
            cn[k] = fmaf(fv, cold[k], iv * gv);
            hn[k] = to_tf32(ov * tanh_(cn[k]));   // tf32-round h for next MMA
        }
        *(float4*)(cptr)     = make_float4(cn[0], cn[1], cn[2], cn[3]);
        *(float4*)(cptr + 4) = make_float4(cn[4], cn[5], cn[6], cn[7]);
        *(float4*)(hptr)     = make_float4(hn[0], hn[1], hn[2], hn[3]);
        *(float4*)(hptr + 4) = make_float4(hn[4], hn[5], hn[6], hn[7]);
    }
}

// ------------------------------- final kernel -------------------------------
__global__ void final_kernel(const float* __restrict__ Wout, const float* __restrict__ bout,
                             float* __restrict__ out) {
    int idx = blockIdx.x * blockDim.x + threadIdx.x;   // 81920
    if (idx >= BATCH * 10) return;
    int b = idx / 10, cls = idx % 10;
    const float* h  = g_h[0] + (size_t)b * HID;        // step 31 wrote g_h[0]
    const float* wv = Wout + (size_t)cls * HID;
    float acc = 0.f;
    #pragma unroll 4
    for (int i = 0; i < HID; i += 4) {
        float4 hv = *(const float4*)(h + i);
        float4 wf = *(const float4*)(wv + i);
        acc = fmaf(hv.x, wf.x, acc);
        acc = fmaf(hv.y, wf.y, acc);
        acc = fmaf(hv.z, wf.z, acc);
        acc = fmaf(hv.w, wf.w, acc);
    }
    out[idx] = acc + bout[cls];
}

// --------------------------------- launch -----------------------------------
extern "C" void kernel_launch(void* const* d_in, const int* in_sizes, int n_in,
                              void* d_out, int out_size) {
    const float* inputs = (const float*)d_in[0];
    const float* h0     = (const float*)d_in[1];
    const float* c0     = (const float*)d_in[2];
    const float* W_ih   = (const float*)d_in[3];
    const float* W_hh   = (const float*)d_in[4];
    const float* b_ih   = (const float*)d_in[5];
    const float* b_hh   = (const float*)d_in[6];
    const float* W_out  = (const float*)d_in[7];
    const float* b_out  = (const float*)d_in[8];
    float* out = (float*)d_out;
    (void)in_sizes; (void)n_in; (void)out_size;

    cudaFuncSetAttribute(step_kernel, cudaFuncAttributeMaxDynamicSharedMemorySize, SMEM_ALLOC);

    prep_x_kernel<<<(BATCH * 3 * 32 * 32 + 255) / 256, 256>>>(inputs);
    prep_misc_kernel<<<(BATCH * HID + 255) / 256, 256>>>(h0, c0, W_ih, W_hh, b_ih, b_hh);

    dim3 grid(BATCH / 128, HID / 32);   // (64, 16) = 1024 CTAs
    for (int t = 0; t < TSTEPS; t++)
        step_kernel<<<grid, THREADS, SMEM_ALLOC>>>(t);

    final_kernel<<<(BATCH * 10 + 255) / 256, 256>>>(W_out, b_out, out);
}

// round 8
// speedup vs baseline: 1.3542x; 1.1317x over previous
#include <cuda_runtime.h>
#include <cstdint>
#include <cstddef>

// ============================================================================
// LSTM (B=8192, H=512, T=32, F=96) on sm_100 via mma.sync.m16n8k8 TF32.
//
// R8 changes vs R7 (passed, 5217us; step 168.8us, L1=80.5%, tensor=44.8%):
//  1. Conflict-free v4 fragment loads: k-permutation gives thread q the
//     16B chunk 4p+q per kb-pair p (f0,f1 -> kb=2p, f2,f3 -> kb=2p+1),
//     identical for A and B; physical swizzle chunk ^= s(row&7),
//     s(g)=((g&1)<<2)|(g>>1) -> every 8-lane wavefront hits all 32 banks.
//     (Old scheme was 2-way conflicted: banks ignore the row, and the XOR
//     spanned only 2 chunks per kb.) Halves LDS wavefronts AND instructions.
//  2. In-register LSTM epilogue: B rows remapped so output col c has
//     gate=(c>>3)&3, unit=nh+(c>>5)*8+(c&7); each thread then holds all 4
//     gates for its (row, unit-pair) cells -> no smem exchange, no extra
//     syncthreads, bias loaded straight from gmem in the epilogue.
// CTA 128x128, 8 warps (2x4) of 64x32, 3-stage cp.async, 2 CTAs/SM.
// ============================================================================

#define DEVI __device__ __forceinline__

#define BATCH   8192
#define HID     512
#define G4      2048
#define TSTEPS  32
#define INFEAT  96
#define NCHUNK  19
#define THREADS 256

#define STAGE_A   16384              // 128 rows x 128B
#define STAGE_B   16384              // 128 rows x 128B
#define STAGE     (STAGE_A + STAGE_B)        // 32768
#define SMEM_NEED (3 * STAGE)                // 98304
#define SMEM_ALLOC (SMEM_NEED + 256)         // align slack

// ------------------------- device scratch (no allocs) -----------------------
__device__ float g_h[2][BATCH * HID];
__device__ float g_c[BATCH * HID];
__device__ float g_bias[G4];
__device__ float g_Whh[G4 * HID];
__device__ float g_Wih[G4 * INFEAT];
__device__ float g_xT[TSTEPS * BATCH * INFEAT];

// ------------------------------ helpers -------------------------------------
DEVI uint32_t smem_u32(const void* p) {
    uint32_t a;
    asm("{ .reg .u64 t; cvta.to.shared.u64 t, %1; cvt.u32.u64 %0, t; }" : "=r"(a) : "l"(p));
    return a;
}
DEVI float to_tf32(float x) {
    uint32_t o;
    asm("cvt.rna.tf32.f32 %0, %1;" : "=r"(o) : "f"(x));
    return __uint_as_float(o);
}
DEVI float ex2f(float x) { float y; asm("ex2.approx.f32 %0, %1;" : "=f"(y) : "f"(x)); return y; }
DEVI float rcpf(float x) { float y; asm("rcp.approx.f32 %0, %1;" : "=f"(y) : "f"(x)); return y; }
DEVI float sigm(float x) { return rcpf(1.0f + ex2f(x * -1.44269504088896f)); }
DEVI float tanh_(float x) { return fmaf(2.0f, sigm(x + x), -1.0f); }

// bank-spreading swizzle term for a row (r mod 8)
DEVI uint32_t swz(uint32_t g) { return ((g & 1u) << 2) | (g >> 1); }

DEVI void cp16(uint32_t sdst, const void* gsrc) {
    asm volatile("cp.async.cg.shared.global [%0], [%1], 16;" :: "r"(sdst), "l"(gsrc) : "memory");
}
DEVI void mma_tf32(float* c, uint32_t a0, uint32_t a1, uint32_t a2, uint32_t a3,
                   uint32_t b0, uint32_t b1) {
    asm volatile(
        "mma.sync.aligned.m16n8k8.row.col.f32.tf32.tf32.f32 "
        "{%0,%1,%2,%3}, {%4,%5,%6,%7}, {%8,%9}, {%0,%1,%2,%3};"
        : "+f"(c[0]), "+f"(c[1]), "+f"(c[2]), "+f"(c[3])
        : "r"(a0), "r"(a1), "r"(a2), "r"(a3), "r"(b0), "r"(b1));
}

// ------------------------------ prep kernels --------------------------------
// inputs[b, ch, t, w] -> g_xT[(t*BATCH + b)*96 + w*3 + ch], tf32-rounded
__global__ void prep_x_kernel(const float* __restrict__ in) {
    int idx = blockIdx.x * blockDim.x + threadIdx.x;
    if (idx >= BATCH * 3 * 32 * 32) return;
    int w  = idx & 31;
    int t  = (idx >> 5) & 31;
    int c3 = idx >> 10;            // b*3 + ch
    int ch = c3 % 3;
    int b  = c3 / 3;
    g_xT[((size_t)t * BATCH + b) * INFEAT + w * 3 + ch] = to_tf32(in[idx]);
}

__global__ void prep_misc_kernel(const float* __restrict__ h0, const float* __restrict__ c0,
                                 const float* __restrict__ Wih, const float* __restrict__ Whh,
                                 const float* __restrict__ bih, const float* __restrict__ bhh) {
    int i = blockIdx.x * blockDim.x + threadIdx.x;
    if (i < BATCH * HID) {
        g_h[0][i] = to_tf32(h0[i]);
        g_c[i]    = c0[i];
    }
    if (i < G4 * HID)    g_Whh[i] = to_tf32(Whh[i]);
    if (i < G4 * INFEAT) g_Wih[i] = to_tf32(Wih[i]);
    if (i < G4)          g_bias[i] = bih[i] + bhh[i];
}

// ------------------------- step kernel chunk loader -------------------------
// A tile: 128 rows x 32 fp32 from [h | x_t]; B tile: 128 rows x 32 fp32 from
// [Whh | Wih] with row r -> gate=(r>>3)&3, unit=nh+(r>>5)*8+(r&7).
// 16B chunks; physical chunk = cc ^ swz(r&7).
DEVI void load_chunk(int kc, uint32_t stA, uint32_t stB, int tid, int brow0, int nh,
                     const float* __restrict__ hin, const float* __restrict__ xT) {
    const float* abase; int apitch;
    if (kc < 16) { abase = hin + (size_t)brow0 * HID + kc * 32;            apitch = HID; }
    else         { abase = xT  + (size_t)brow0 * INFEAT + (kc - 16) * 32;  apitch = INFEAT; }
    #pragma unroll
    for (int u = 0; u < 4; u++) {
        int ch = tid + u * THREADS;          // 0..1023
        int r = ch >> 3, cc = ch & 7;
        uint32_t dst = stA + r * 128 + ((cc ^ swz(r & 7)) << 4);
        cp16(dst, abase + (size_t)r * apitch + cc * 4);
    }
    const float* wbase; int wpitch, kk;
    if (kc < 16) { wbase = g_Whh; wpitch = HID;    kk = kc * 32; }
    else         { wbase = g_Wih; wpitch = INFEAT; kk = (kc - 16) * 32; }
    #pragma unroll
    for (int u = 0; u < 4; u++) {
        int ch = tid + u * THREADS;          // 0..1023
        int r = ch >> 3, cc = ch & 7;
        int wrow = ((r >> 3) & 3) * HID + nh + ((r >> 5) << 3) + (r & 7);  // gate*512+unit
        uint32_t dst = stB + r * 128 + ((cc ^ swz(r & 7)) << 4);
        cp16(dst, wbase + (size_t)wrow * wpitch + kk + cc * 4);
    }
    asm volatile("cp.async.commit_group;" ::: "memory");
}

// ------------------------------- step kernel --------------------------------
__global__ void __launch_bounds__(THREADS, 2) step_kernel(int t) {
    extern __shared__ char dsm[];
    uint32_t sb = smem_u32(dsm);
    sb = (sb + 127u) & ~127u;

    const int tid  = threadIdx.x;
    const int warp = tid >> 5, lane = tid & 31;
    const int wm = warp >> 2, wn = warp & 3;     // 2x4 warp grid
    const int g  = lane >> 2, q = lane & 3;
    const int nh    = blockIdx.y * 32;           // hidden-unit slice base
    const int brow0 = blockIdx.x * 128;          // batch-row base

    const float* __restrict__ hin  = g_h[t & 1];
    float*       __restrict__ hout = g_h[(t + 1) & 1];
    const float* __restrict__ xT   = g_xT + (size_t)t * BATCH * INFEAT;

    load_chunk(0, sb,             sb + STAGE_A,             tid, brow0, nh, hin, xT);
    load_chunk(1, sb + STAGE,     sb + STAGE + STAGE_A,     tid, brow0, nh, hin, xT);

    float acc[4][4][4] = {};
    const uint32_t sg = swz((uint32_t)g);

    for (int kc = 0; kc < NCHUNK; kc++) {
        if (kc < NCHUNK - 1) asm volatile("cp.async.wait_group 1;" ::: "memory");
        else                 asm volatile("cp.async.wait_group 0;" ::: "memory");
        __syncthreads();
        if (kc + 2 < NCHUNK) {
            int s = (kc + 2) % 3;
            load_chunk(kc + 2, sb + s * STAGE, sb + s * STAGE + STAGE_A, tid, brow0, nh, hin, xT);
        }
        const uint32_t stA = sb + (kc % 3) * STAGE;
        const uint32_t stB = stA + STAGE_A;

        #pragma unroll
        for (int p = 0; p < 2; p++) {           // kb-pair: covers kb=2p, 2p+1
            const uint32_t choff = ((uint32_t)((4 * p + q) ^ sg)) << 4;
            // B fragments: 4 n-tiles, one v4 each (f0,f1 -> kb lo; f2,f3 -> hi)
            uint32_t bw[4][4];
            #pragma unroll
            for (int n = 0; n < 4; n++) {
                uint32_t rb = stB + (uint32_t)(wn * 32 + n * 8 + g) * 128 + choff;
                asm volatile("ld.shared.v4.u32 {%0,%1,%2,%3}, [%4];"
                             : "=r"(bw[n][0]), "=r"(bw[n][1]), "=r"(bw[n][2]), "=r"(bw[n][3])
                             : "r"(rb));
            }
            #pragma unroll
            for (int m = 0; m < 4; m++) {
                uint32_t ra = stA + (uint32_t)(wm * 64 + m * 16 + g) * 128 + choff;
                uint32_t x0, x1, x2, x3, y0, y1, y2, y3;
                asm volatile("ld.shared.v4.u32 {%0,%1,%2,%3}, [%4];"
                             : "=r"(x0), "=r"(x1), "=r"(x2), "=r"(x3) : "r"(ra));
                asm volatile("ld.shared.v4.u32 {%0,%1,%2,%3}, [%4];"
                             : "=r"(y0), "=r"(y1), "=r"(y2), "=r"(y3) : "r"(ra + 8 * 128));
                #pragma unroll
                for (int n = 0; n < 4; n++) {
                    mma_tf32(acc[m][n], x0, y0, x1, y1, bw[n][0], bw[n][1]);  // kb = 2p
                    mma_tf32(acc[m][n], x2, y2, x3, y3, bw[n][2], bw[n][3]);  // kb = 2p+1
                }
            }
        }
    }

    // -------------------- in-register LSTM epilogue -------------------------
    // acc[m][n][slot]: slot0=(row g,   unit 2q), slot1=(g,   2q+1),
    //                  slot2=(row g+8, unit 2q), slot3=(g+8, 2q+1); gate = n.
    const int u0 = nh + wn * 8 + 2 * q;
    const float2 bi = *(const float2*)(g_bias + 0 * HID + u0);
    const float2 bf = *(const float2*)(g_bias + 1 * HID + u0);
    const float2 bg = *(const float2*)(g_bias + 2 * HID + u0);
    const float2 bo = *(const float2*)(g_bias + 3 * HID + u0);

    #pragma unroll
    for (int m = 0; m < 4; m++) {
        #pragma unroll
        for (int rh = 0; rh < 2; rh++) {
            const int row = brow0 + wm * 64 + m * 16 + g + rh * 8;
            const int s0 = rh * 2;              // slot for unit u0
            float* cptr = g_c  + (size_t)row * HID + u0;
            float* hptr = hout + (size_t)row * HID + u0;
            float2 cv = *(const float2*)(cptr);

            float i0 = sigm (acc[m][0][s0]     + bi.x);
            float f0 = sigm (acc[m][1][s0]     + bf.x);
            float g0 = tanh_(acc[m][2][s0]     + bg.x);
            float o0 = sigm (acc[m][3][s0]     + bo.x);
            float i1 = sigm (acc[m][0][s0 + 1] + bi.y);
            float f1 = sigm (acc[m][1][s0 + 1] + bf.y);
            float g1 = tanh_(acc[m][2][s0 + 1] + bg.y);
            float o1 = sigm (acc[m][3][s0 + 1] + bo.y);

            float cn0 = fmaf(f0, cv.x, i0 * g0);
            float cn1 = fmaf(f1, cv.y, i1 * g1);
            *(float2*)(cptr) = make_float2(cn0, cn1);
            *(float2*)(hptr) = make_float2(to_tf32(o0 * tanh_(cn0)),
                                           to_tf32(o1 * tanh_(cn1)));
        }
    }
}

// ------------------------------- final kernel -------------------------------
__global__ void final_kernel(const float* __restrict__ Wout, const float* __restrict__ bout,
                             float* __restrict__ out) {
    int idx = blockIdx.x * blockDim.x + threadIdx.x;   // 81920
    if (idx >= BATCH * 10) return;
    int b = idx / 10, cls = idx % 10;
    const float* h  = g_h[0] + (size_t)b * HID;        // step 31 wrote g_h[0]
    const float* wv = Wout + (size_t)cls * HID;
    float acc = 0.f;
    #pragma unroll 4
    for (int i = 0; i < HID; i += 4) {
        float4 hv = *(const float4*)(h + i);
        float4 wf = *(const float4*)(wv + i);
        acc = fmaf(hv.x, wf.x, acc);
        acc = fmaf(hv.y, wf.y, acc);
        acc = fmaf(hv.z, wf.z, acc);
        acc = fmaf(hv.w, wf.w, acc);
    }
    out[idx] = acc + bout[cls];
}

// --------------------------------- launch -----------------------------------
extern "C" void kernel_launch(void* const* d_in, const int* in_sizes, int n_in,
                              void* d_out, int out_size) {
    const float* inputs = (const float*)d_in[0];
    const float* h0     = (const float*)d_in[1];
    const float* c0     = (const float*)d_in[2];
    const float* W_ih   = (const float*)d_in[3];
    const float* W_hh   = (const float*)d_in[4];
    const float* b_ih   = (const float*)d_in[5];
    const float* b_hh   = (const float*)d_in[6];
    const float* W_out  = (const float*)d_in[7];
    const float* b_out  = (const float*)d_in[8];
    float* out = (float*)d_out;
    (void)in_sizes; (void)n_in; (void)out_size;

    cudaFuncSetAttribute(step_kernel, cudaFuncAttributeMaxDynamicSharedMemorySize, SMEM_ALLOC);

    prep_x_kernel<<<(BATCH * 3 * 32 * 32 + 255) / 256, 256>>>(inputs);
    prep_misc_kernel<<<(BATCH * HID + 255) / 256, 256>>>(h0, c0, W_ih, W_hh, b_ih, b_hh);

    dim3 grid(BATCH / 128, HID / 32);   // (64, 16) = 1024 CTAs
    for (int t = 0; t < TSTEPS; t++)
        step_kernel<<<grid, THREADS, SMEM_ALLOC>>>(t);

    final_kernel<<<(BATCH * 10 + 255) / 256, 256>>>(W_out, b_out, out);
}

// round 9
// speedup vs baseline: 1.4475x; 1.0689x over previous
#include <cuda_runtime.h>
#include <cstdint>
#include <cstddef>

// ============================================================================
// LSTM (B=8192, H=512, T=32, F=96) on sm_100 via mma.sync.m16n8k8 TF32.
//
// R9 change vs R8 (passed 4610us; step 154us, alu=50.8%, tensor=50.1%,
// issue=44.9%): W is pre-materialized into the EXACT smem tile image
// (gate-remapped rows + XOR bank swizzle baked in) as g_Wt[16][19][128x32].
// The mainloop B load is now a linear 16KB block copy: zero per-chunk ALU
// (was ~40 ops/thread/chunk of wrow+swizzle math) and perfectly coalesced
// L2 sectors (was 16B picks from 2KB-strided rows). g_Wt = 4.75MB ->
// L2-resident across all 32 steps. Everything else (conflict-free v4
// fragment k-permutation, in-register epilogue, 3-stage cp.async,
// 128x128 CTA, 2 CTAs/SM) unchanged.
// ============================================================================

#define DEVI __device__ __forceinline__

#define BATCH   8192
#define HID     512
#define G4      2048
#define TSTEPS  32
#define INFEAT  96
#define NCHUNK  19
#define THREADS 256

#define STAGE_A   16384              // 128 rows x 128B
#define STAGE_B   16384              // 128 rows x 128B
#define STAGE     (STAGE_A + STAGE_B)        // 32768
#define SMEM_NEED (3 * STAGE)                // 98304
#define SMEM_ALLOC (SMEM_NEED + 256)         // align slack

#define WT_FLOATS (16 * NCHUNK * 128 * 32)   // 1,245,184 floats = 4.75MB

// ------------------------- device scratch (no allocs) -----------------------
__device__ float g_h[2][BATCH * HID];
__device__ float g_c[BATCH * HID];
__device__ float g_bias[G4];
__device__ float g_Wt[WT_FLOATS];            // pre-tiled, pre-swizzled W
__device__ float g_xT[TSTEPS * BATCH * INFEAT];

// ------------------------------ helpers -------------------------------------
DEVI uint32_t smem_u32(const void* p) {
    uint32_t a;
    asm("{ .reg .u64 t; cvta.to.shared.u64 t, %1; cvt.u32.u64 %0, t; }" : "=r"(a) : "l"(p));
    return a;
}
DEVI float to_tf32(float x) {
    uint32_t o;
    asm("cvt.rna.tf32.f32 %0, %1;" : "=r"(o) : "f"(x));
    return __uint_as_float(o);
}
DEVI float ex2f(float x) { float y; asm("ex2.approx.f32 %0, %1;" : "=f"(y) : "f"(x)); return y; }
DEVI float rcpf(float x) { float y; asm("rcp.approx.f32 %0, %1;" : "=f"(y) : "f"(x)); return y; }
DEVI float sigm(float x) { return rcpf(1.0f + ex2f(x * -1.44269504088896f)); }
DEVI float tanh_(float x) { return fmaf(2.0f, sigm(x + x), -1.0f); }

// bank-spreading swizzle term for a row (r mod 8)
DEVI uint32_t swz(uint32_t g) { return ((g & 1u) << 2) | (g >> 1); }

DEVI void cp16(uint32_t sdst, const void* gsrc) {
    asm volatile("cp.async.cg.shared.global [%0], [%1], 16;" :: "r"(sdst), "l"(gsrc) : "memory");
}
DEVI void mma_tf32(float* c, uint32_t a0, uint32_t a1, uint32_t a2, uint32_t a3,
                   uint32_t b0, uint32_t b1) {
    asm volatile(
        "mma.sync.aligned.m16n8k8.row.col.f32.tf32.tf32.f32 "
        "{%0,%1,%2,%3}, {%4,%5,%6,%7}, {%8,%9}, {%0,%1,%2,%3};"
        : "+f"(c[0]), "+f"(c[1]), "+f"(c[2]), "+f"(c[3])
        : "r"(a0), "r"(a1), "r"(a2), "r"(a3), "r"(b0), "r"(b1));
}

// ------------------------------ prep kernels --------------------------------
// inputs[b, ch, t, w] -> g_xT[(t*BATCH + b)*96 + w*3 + ch], tf32-rounded
__global__ void prep_x_kernel(const float* __restrict__ in) {
    int idx = blockIdx.x * blockDim.x + threadIdx.x;
    if (idx >= BATCH * 3 * 32 * 32) return;
    int w  = idx & 31;
    int t  = (idx >> 5) & 31;
    int c3 = idx >> 10;            // b*3 + ch
    int ch = c3 % 3;
    int b  = c3 / 3;
    g_xT[((size_t)t * BATCH + b) * INFEAT + w * 3 + ch] = to_tf32(in[idx]);
}

__global__ void prep_misc_kernel(const float* __restrict__ h0, const float* __restrict__ c0,
                                 const float* __restrict__ bih, const float* __restrict__ bhh) {
    int i = blockIdx.x * blockDim.x + threadIdx.x;
    if (i < BATCH * HID) {
        g_h[0][i] = to_tf32(h0[i]);
        g_c[i]    = c0[i];
    }
    if (i < G4) g_bias[i] = bih[i] + bhh[i];
}

// Build g_Wt: for (nhi, kc) a 128x32 tile whose row r is weight row
// wrow = gate(r)*512 + nhi*32 + unit(r), columns kk..kk+31, stored with the
// bank swizzle (chunk cc_dst = cc_src ^ swz(r&7)) already applied.
__global__ void prep_w_kernel(const float* __restrict__ Wih, const float* __restrict__ Whh) {
    int idx = blockIdx.x * blockDim.x + threadIdx.x;
    if (idx >= WT_FLOATS) return;
    int pos = idx & 4095;                 // within 128x32 tile
    int kc  = (idx >> 12) % NCHUNK;
    int nhi = idx / (NCHUNK * 4096);
    int r   = pos >> 5;
    int c   = pos & 31;
    int cc_dst = c >> 2, j = c & 3;
    int cc_src = cc_dst ^ (int)swz((uint32_t)(r & 7));
    int k_local = cc_src * 4 + j;
    int wrow = ((r >> 3) & 3) * HID + nhi * 32 + ((r >> 5) << 3) + (r & 7);
    float v;
    if (kc < 16) v = Whh[(size_t)wrow * HID    + kc * 32        + k_local];
    else         v = Wih[(size_t)wrow * INFEAT + (kc - 16) * 32 + k_local];
    g_Wt[idx] = to_tf32(v);
}

// ------------------------- step kernel chunk loader -------------------------
// A tile: 128 rows x 32 fp32 from [h | x_t] (swizzled on store).
// B tile: straight 16KB block copy from pre-tiled g_Wt (swizzle baked in).
DEVI void load_chunk(int kc, uint32_t stA, uint32_t stB, int tid, int brow0, int nhi,
                     const float* __restrict__ hin, const float* __restrict__ xT) {
    const float* abase; int apitch;
    if (kc < 16) { abase = hin + (size_t)brow0 * HID + kc * 32;            apitch = HID; }
    else         { abase = xT  + (size_t)brow0 * INFEAT + (kc - 16) * 32;  apitch = INFEAT; }
    #pragma unroll
    for (int u = 0; u < 4; u++) {
        int ch = tid + u * THREADS;          // 0..1023
        int r = ch >> 3, cc = ch & 7;
        uint32_t dst = stA + r * 128 + ((cc ^ swz(r & 7)) << 4);
        cp16(dst, abase + (size_t)r * apitch + cc * 4);
    }
    const float* wsrc = g_Wt + ((size_t)(nhi * NCHUNK + kc) << 12);
    #pragma unroll
    for (int u = 0; u < 4; u++) {
        int ch = tid + u * THREADS;          // 0..1023 -> linear 16B chunks
        cp16(stB + ch * 16, wsrc + ch * 4);
    }
    asm volatile("cp.async.commit_group;" ::: "memory");
}

// ------------------------------- step kernel --------------------------------
__global__ void __launch_bounds__(THREADS, 2) step_kernel(int t) {
    extern __shared__ char dsm[];
    uint32_t sb = smem_u32(dsm);
    sb = (sb + 127u) & ~127u;

    const int tid  = threadIdx.x;
    const int warp = tid >> 5, lane = tid & 31;
    const int wm = warp >> 2, wn = warp & 3;     // 2x4 warp grid
    const int g  = lane >> 2, q = lane & 3;
    const int nhi   = blockIdx.y;                // hidden-unit slice index
    const int nh    = nhi * 32;
    const int brow0 = blockIdx.x * 128;          // batch-row base

    const float* __restrict__ hin  = g_h[t & 1];
    float*       __restrict__ hout = g_h[(t + 1) & 1];
    const float* __restrict__ xT   = g_xT + (size_t)t * BATCH * INFEAT;

    load_chunk(0, sb,             sb + STAGE_A,             tid, brow0, nhi, hin, xT);
    load_chunk(1, sb + STAGE,     sb + STAGE + STAGE_A,     tid, brow0, nhi, hin, xT);

    float acc[4][4][4] = {};
    const uint32_t sg = swz((uint32_t)g);

    for (int kc = 0; kc < NCHUNK; kc++) {
        if (kc < NCHUNK - 1) asm volatile("cp.async.wait_group 1;" ::: "memory");
        else                 asm volatile("cp.async.wait_group 0;" ::: "memory");
        __syncthreads();
        if (kc + 2 < NCHUNK) {
            int s = (kc + 2) % 3;
            load_chunk(kc + 2, sb + s * STAGE, sb + s * STAGE + STAGE_A, tid, brow0, nhi, hin, xT);
        }
        const uint32_t stA = sb + (kc % 3) * STAGE;
        const uint32_t stB = stA + STAGE_A;

        #pragma unroll
        for (int p = 0; p < 2; p++) {           // kb-pair: covers kb=2p, 2p+1
            const uint32_t choff = ((uint32_t)((4 * p + q) ^ sg)) << 4;
            // B fragments: 4 n-tiles, one v4 each (f0,f1 -> kb lo; f2,f3 -> hi)
            uint32_t bw[4][4];
            #pragma unroll
            for (int n = 0; n < 4; n++) {
                uint32_t rb = stB + (uint32_t)(wn * 32 + n * 8 + g) * 128 + choff;
                asm volatile("ld.shared.v4.u32 {%0,%1,%2,%3}, [%4];"
                             : "=r"(bw[n][0]), "=r"(bw[n][1]), "=r"(bw[n][2]), "=r"(bw[n][3])
                             : "r"(rb));
            }
            #pragma unroll
            for (int m = 0; m < 4; m++) {
                uint32_t ra = stA + (uint32_t)(wm * 64 + m * 16 + g) * 128 + choff;
                uint32_t x0, x1, x2, x3, y0, y1, y2, y3;
                asm volatile("ld.shared.v4.u32 {%0,%1,%2,%3}, [%4];"
                             : "=r"(x0), "=r"(x1), "=r"(x2), "=r"(x3) : "r"(ra));
                asm volatile("ld.shared.v4.u32 {%0,%1,%2,%3}, [%4];"
                             : "=r"(y0), "=r"(y1), "=r"(y2), "=r"(y3) : "r"(ra + 8 * 128));
                #pragma unroll
                for (int n = 0; n < 4; n++) {
                    mma_tf32(acc[m][n], x0, y0, x1, y1, bw[n][0], bw[n][1]);  // kb = 2p
                    mma_tf32(acc[m][n], x2, y2, x3, y3, bw[n][2], bw[n][3]);  // kb = 2p+1
                }
            }
        }
    }

    // -------------------- in-register LSTM epilogue -------------------------
    // acc[m][n][slot]: slot0=(row g,   unit 2q), slot1=(g,   2q+1),
    //                  slot2=(row g+8, unit 2q), slot3=(g+8, 2q+1); gate = n.
    const int u0 = nh + wn * 8 + 2 * q;
    const float2 bi = *(const float2*)(g_bias + 0 * HID + u0);
    const float2 bf = *(const float2*)(g_bias + 1 * HID + u0);
    const float2 bg = *(const float2*)(g_bias + 2 * HID + u0);
    const float2 bo = *(const float2*)(g_bias + 3 * HID + u0);

    #pragma unroll
    for (int m = 0; m < 4; m++) {
        #pragma unroll
        for (int rh = 0; rh < 2; rh++) {
            const int row = brow0 + wm * 64 + m * 16 + g + rh * 8;
            const int s0 = rh * 2;              // slot for unit u0
            float* cptr = g_c  + (size_t)row * HID + u0;
            float* hptr = hout + (size_t)row * HID + u0;
            float2 cv = *(const float2*)(cptr);

            float i0 = sigm (acc[m][0][s0]     + bi.x);
            float f0 = sigm (acc[m][1][s0]     + bf.x);
            float g0 = tanh_(acc[m][2][s0]     + bg.x);
            float o0 = sigm (acc[m][3][s0]     + bo.x);
            float i1 = sigm (acc[m][0][s0 + 1] + bi.y);
            float f1 = sigm (acc[m][1][s0 + 1] + bf.y);
            float g1 = tanh_(acc[m][2][s0 + 1] + bg.y);
            float o1 = sigm (acc[m][3][s0 + 1] + bo.y);

            float cn0 = fmaf(f0, cv.x, i0 * g0);
            float cn1 = fmaf(f1, cv.y, i1 * g1);
            *(float2*)(cptr) = make_float2(cn0, cn1);
            *(float2*)(hptr) = make_float2(to_tf32(o0 * tanh_(cn0)),
                                           to_tf32(o1 * tanh_(cn1)));
        }
    }
}

// ------------------------------- final kernel -------------------------------
__global__ void final_kernel(const float* __restrict__ Wout, const float* __restrict__ bout,
                             float* __restrict__ out) {
    int idx = blockIdx.x * blockDim.x + threadIdx.x;   // 81920
    if (idx >= BATCH * 10) return;
    int b = idx / 10, cls = idx % 10;
    const float* h  = g_h[0] + (size_t)b * HID;        // step 31 wrote g_h[0]
    const float* wv = Wout + (size_t)cls * HID;
    float acc = 0.f;
    #pragma unroll 4
    for (int i = 0; i < HID; i += 4) {
        float4 hv = *(const float4*)(h + i);
        float4 wf = *(const float4*)(wv + i);
        acc = fmaf(hv.x, wf.x, acc);
        acc = fmaf(hv.y, wf.y, acc);
        acc = fmaf(hv.z, wf.z, acc);
        acc = fmaf(hv.w, wf.w, acc);
    }
    out[idx] = acc + bout[cls];
}

// --------------------------------- launch -----------------------------------
extern "C" void kernel_launch(void* const* d_in, const int* in_sizes, int n_in,
                              void* d_out, int out_size) {
    const float* inputs = (const float*)d_in[0];
    const float* h0     = (const float*)d_in[1];
    const float* c0     = (const float*)d_in[2];
    const float* W_ih   = (const float*)d_in[3];
    const float* W_hh   = (const float*)d_in[4];
    const float* b_ih   = (const float*)d_in[5];
    const float* b_hh   = (const float*)d_in[6];
    const float* W_out  = (const float*)d_in[7];
    const float* b_out  = (const float*)d_in[8];
    float* out = (float*)d_out;
    (void)in_sizes; (void)n_in; (void)out_size;

    cudaFuncSetAttribute(step_kernel, cudaFuncAttributeMaxDynamicSharedMemorySize, SMEM_ALLOC);

    prep_x_kernel<<<(BATCH * 3 * 32 * 32 + 255) / 256, 256>>>(inputs);
    prep_misc_kernel<<<(BATCH * HID + 255) / 256, 256>>>(h0, c0, b_ih, b_hh);
    prep_w_kernel<<<(WT_FLOATS + 255) / 256, 256>>>(W_ih, W_hh);

    dim3 grid(BATCH / 128, HID / 32);   // (64, 16) = 1024 CTAs
    for (int t = 0; t < TSTEPS; t++)
        step_kernel<<<grid, THREADS, SMEM_ALLOC>>>(t);

    final_kernel<<<(BATCH * 10 + 255) / 256, 256>>>(W_out, b_out, out);
}

// round 11
// speedup vs baseline: 1.5284x; 1.0559x over previous
#include <cuda_runtime.h>
#include <cstdint>
#include <cstddef>

// ============================================================================
// LSTM (B=8192, H=512, T=32, F=96) on sm_100 via mma.sync.m16n8k8 TF32.
//
// R10/R11 change vs R9 (passed 4313us; step 144us, alu=44%, tensor=53.5%):
// compile-time stage indices everywhere. The kc loop is structured so the
// 3-stage rotation is a template parameter: all fragment LDS addresses are
// [persistent-reg + immediate] (4 base regs computed once), and cp.async
// uses 2 persistent dst regs + src pointers bumped by one ADD per chunk.
// This kills the ~150 ALU ops/warp/chunk of per-chunk address rebuild that
// R9's runtime (kc%3)*STAGE base forced (alu pipe was co-binding with
// tensor on issue slots). Math is bit-identical to R9.
// ============================================================================

#define DEVI __device__ __forceinline__

#define BATCH   8192
#define HID     512
#define G4      2048
#define TSTEPS  32
#define INFEAT  96
#define NCHUNK  19
#define THREADS 256

#define STAGE     32768              // A 16KB | B 16KB
#define SMEM_NEED (3 * STAGE)
#define SMEM_ALLOC (SMEM_NEED + 256)

#define WT_FLOATS (16 * NCHUNK * 128 * 32)   // 4.75MB pre-tiled W

// ------------------------- device scratch (no allocs) -----------------------
__device__ float g_h[2][BATCH * HID];
__device__ float g_c[BATCH * HID];
__device__ float g_bias[G4];
__device__ float g_Wt[WT_FLOATS];
__device__ float g_xT[TSTEPS * BATCH * INFEAT];

// ------------------------------ helpers -------------------------------------
DEVI uint32_t smem_u32(const void* p) {
    uint32_t a;
    asm("{ .reg .u64 t; cvta.to.shared.u64 t, %1; cvt.u32.u64 %0, t; }" : "=r"(a) : "l"(p));
    return a;
}
DEVI float to_tf32(float x) {
    uint32_t o;
    asm("cvt.rna.tf32.f32 %0, %1;" : "=r"(o) : "f"(x));
    return __uint_as_float(o);
}
DEVI float ex2f(float x) { float y; asm("ex2.approx.f32 %0, %1;" : "=f"(y) : "f"(x)); return y; }
DEVI float rcpf(float x) { float y; asm("rcp.approx.f32 %0, %1;" : "=f"(y) : "f"(x)); return y; }
DEVI float sigm(float x) { return rcpf(1.0f + ex2f(x * -1.44269504088896f)); }
DEVI float tanh_(float x) { return fmaf(2.0f, sigm(x + x), -1.0f); }

DEVI uint32_t swz(uint32_t g) { return ((g & 1u) << 2) | (g >> 1); }

DEVI void cp16(uint32_t sdst, const void* gsrc) {
    asm volatile("cp.async.cg.shared.global [%0], [%1], 16;" :: "r"(sdst), "l"(gsrc) : "memory");
}
DEVI void mma_tf32(float* c, uint32_t a0, uint32_t a1, uint32_t a2, uint32_t a3,
                   uint32_t b0, uint32_t b1) {
    asm volatile(
        "mma.sync.aligned.m16n8k8.row.col.f32.tf32.tf32.f32 "
        "{%0,%1,%2,%3}, {%4,%5,%6,%7}, {%8,%9}, {%0,%1,%2,%3};"
        : "+f"(c[0]), "+f"(c[1]), "+f"(c[2]), "+f"(c[3])
        : "r"(a0), "r"(a1), "r"(a2), "r"(a3), "r"(b0), "r"(b1));
}

// ------------------------------ prep kernels --------------------------------
__global__ void prep_x_kernel(const float* __restrict__ in) {
    int idx = blockIdx.x * blockDim.x + threadIdx.x;
    if (idx >= BATCH * 3 * 32 * 32) return;
    int w  = idx & 31;
    int t  = (idx >> 5) & 31;
    int c3 = idx >> 10;
    int ch = c3 % 3;
    int b  = c3 / 3;
    g_xT[((size_t)t * BATCH + b) * INFEAT + w * 3 + ch] = to_tf32(in[idx]);
}

__global__ void prep_misc_kernel(const float* __restrict__ h0, const float* __restrict__ c0,
                                 const float* __restrict__ bih, const float* __restrict__ bhh) {
    int i = blockIdx.x * blockDim.x + threadIdx.x;
    if (i < BATCH * HID) {
        g_h[0][i] = to_tf32(h0[i]);
        g_c[i]    = c0[i];
    }
    if (i < G4) g_bias[i] = bih[i] + bhh[i];
}

// g_Wt[(nhi*NCHUNK + kc)*4096 + r*32 + c]: row r = gate(r)*512 + nhi*32 +
// unit(r), swizzle (chunk ^= swz(r&7)) baked in.
__global__ void prep_w_kernel(const float* __restrict__ Wih, const float* __restrict__ Whh) {
    int idx = blockIdx.x * blockDim.x + threadIdx.x;
    if (idx >= WT_FLOATS) return;
    int pos = idx & 4095;
    int kc  = (idx >> 12) % NCHUNK;
    int nhi = idx / (NCHUNK * 4096);
    int r   = pos >> 5;
    int c   = pos & 31;
    int cc_dst = c >> 2, j = c & 3;
    int cc_src = cc_dst ^ (int)swz((uint32_t)(r & 7));
    int k_local = cc_src * 4 + j;
    int wrow = ((r >> 3) & 3) * HID + nhi * 32 + ((r >> 5) << 3) + (r & 7);
    float v;
    if (kc < 16) v = Whh[(size_t)wrow * HID    + kc * 32        + k_local];
    else         v = Wih[(size_t)wrow * INFEAT + (kc - 16) * 32 + k_local];
    g_Wt[idx] = to_tf32(v);
}

// --------------------- templated loader / compute bodies --------------------
// S = pipeline stage (compile-time). AP = A source row-group stride in floats
// (32 rows x pitch): 16384 for h, 3072 for x.
template<int S, int AP>
DEVI void load_stage(uint32_t dstA, uint32_t dstB,
                     const float* __restrict__ srcA, const float* __restrict__ srcB) {
    #pragma unroll
    for (int u = 0; u < 4; u++)
        cp16(dstA + S * STAGE + u * 4096, srcA + (size_t)u * AP);
    #pragma unroll
    for (int u = 0; u < 4; u++)
        cp16(dstB + S * STAGE + u * 4096, srcB + u * 1024);
    asm volatile("cp.async.commit_group;" ::: "memory");
}

template<int S>
DEVI void mma_chunk(float (&acc)[4][4][4],
                    uint32_t RA0, uint32_t RA1, uint32_t RB0, uint32_t RB1) {
    #pragma unroll
    for (int p = 0; p < 2; p++) {
        const uint32_t RA = (p ? RA1 : RA0) + S * STAGE;
        const uint32_t RB = (p ? RB1 : RB0) + S * STAGE + 16384;
        uint32_t bw[4][4];
        #pragma unroll
        for (int n = 0; n < 4; n++)
            asm volatile("ld.shared.v4.u32 {%0,%1,%2,%3}, [%4];"
                         : "=r"(bw[n][0]), "=r"(bw[n][1]), "=r"(bw[n][2]), "=r"(bw[n][3])
                         : "r"(RB + n * 1024));
        #pragma unroll
        for (int m = 0; m < 4; m++) {
            uint32_t x0, x1, x2, x3, y0, y1, y2, y3;
            asm volatile("ld.shared.v4.u32 {%0,%1,%2,%3}, [%4];"
                         : "=r"(x0), "=r"(x1), "=r"(x2), "=r"(x3) : "r"(RA + m * 2048));
            asm volatile("ld.shared.v4.u32 {%0,%1,%2,%3}, [%4];"
                         : "=r"(y0), "=r"(y1), "=r"(y2), "=r"(y3) : "r"(RA + m * 2048 + 1024));
            #pragma unroll
            for (int n = 0; n < 4; n++) {
                mma_tf32(acc[m][n], x0, y0, x1, y1, bw[n][0], bw[n][1]);
                mma_tf32(acc[m][n], x2, y2, x3, y3, bw[n][2], bw[n][3]);
            }
        }
    }
}

#define WAITG(N) asm volatile("cp.async.wait_group " #N ";" ::: "memory")

// ------------------------------- step kernel --------------------------------
__global__ void __launch_bounds__(THREADS, 2) step_kernel(int t) {
    extern __shared__ char dsm[];
    uint32_t sb = smem_u32(dsm);
    sb = (sb + 127u) & ~127u;

    const int tid  = threadIdx.x;
    const int warp = tid >> 5, lane = tid & 31;
    const int wm = warp >> 2, wn = warp & 3;
    const int g  = lane >> 2, q = lane & 3;
    const int nhi   = blockIdx.y;
    const int nh    = nhi * 32;
    const int brow0 = blockIdx.x * 128;

    const float* __restrict__ hin  = g_h[t & 1];
    float*       __restrict__ hout = g_h[(t + 1) & 1];
    const float* __restrict__ xT   = g_xT + (size_t)t * BATCH * INFEAT;

    // persistent cp.async addressing
    const int r0 = tid >> 3, cc0 = tid & 7;
    const uint32_t dstA = sb + r0 * 128 + (((uint32_t)cc0 ^ swz((uint32_t)(r0 & 7))) << 4);
    const uint32_t dstB = sb + 16384 + tid * 16;
    const float* srcA  = hin + (size_t)(brow0 + r0) * HID + cc0 * 4;
    const float* srcB  = g_Wt + ((size_t)(nhi * NCHUNK) << 12) + tid * 4;
    const float* srcAx = xT + (size_t)(brow0 + r0) * INFEAT + cc0 * 4;

    // persistent fragment base registers (k-permutation chunk (4p+q)^swz(g))
    const uint32_t sg  = swz((uint32_t)g);
    const uint32_t RA0 = sb + (uint32_t)(wm * 64 + g) * 128 + (((uint32_t)q ^ sg) << 4);
    const uint32_t RA1 = sb + (uint32_t)(wm * 64 + g) * 128 + (((uint32_t)(4 + q) ^ sg) << 4);
    const uint32_t RB0 = sb + (uint32_t)(wn * 32 + g) * 128 + (((uint32_t)q ^ sg) << 4);
    const uint32_t RB1 = sb + (uint32_t)(wn * 32 + g) * 128 + (((uint32_t)(4 + q) ^ sg) << 4);

    // prologue: chunks 0, 1
    load_stage<0, 16384>(dstA, dstB, srcA,      srcB);
    load_stage<1, 16384>(dstA, dstB, srcA + 32, srcB + 4096);
    srcA += 64; srcB += 8192;

    float acc[4][4][4] = {};

    // kc = 0..11 (4 groups of 3; loads cover chunks 2..13, all h)
    for (int i = 0; i < 4; i++) {
        WAITG(1); __syncthreads();
        load_stage<2, 16384>(dstA, dstB, srcA, srcB); srcA += 32; srcB += 4096;
        mma_chunk<0>(acc, RA0, RA1, RB0, RB1);

        WAITG(1); __syncthreads();
        load_stage<0, 16384>(dstA, dstB, srcA, srcB); srcA += 32; srcB += 4096;
        mma_chunk<1>(acc, RA0, RA1, RB0, RB1);

        WAITG(1); __syncthreads();
        load_stage<1, 16384>(dstA, dstB, srcA, srcB); srcA += 32; srcB += 4096;
        mma_chunk<2>(acc, RA0, RA1, RB0, RB1);
    }

    // kc = 12 (load chunk 14, h)
    WAITG(1); __syncthreads();
    load_stage<2, 16384>(dstA, dstB, srcA, srcB); srcA += 32; srcB += 4096;
    mma_chunk<0>(acc, RA0, RA1, RB0, RB1);
    // kc = 13 (load chunk 15, h)
    WAITG(1); __syncthreads();
    load_stage<0, 16384>(dstA, dstB, srcA, srcB); srcB += 4096;
    mma_chunk<1>(acc, RA0, RA1, RB0, RB1);
    // kc = 14 (load chunk 16, x)
    WAITG(1); __syncthreads();
    load_stage<1, 3072>(dstA, dstB, srcAx, srcB); srcB += 4096;
    mma_chunk<2>(acc, RA0, RA1, RB0, RB1);
    // kc = 15 (load chunk 17, x)
    WAITG(1); __syncthreads();
    load_stage<2, 3072>(dstA, dstB, srcAx + 32, srcB); srcB += 4096;
    mma_chunk<0>(acc, RA0, RA1, RB0, RB1);
    // kc = 16 (load chunk 18, x)
    WAITG(1); __syncthreads();
    load_stage<0, 3072>(dstA, dstB, srcAx + 64, srcB);
    mma_chunk<1>(acc, RA0, RA1, RB0, RB1);
    // kc = 17
    WAITG(1); __syncthreads();
    mma_chunk<2>(acc, RA0, RA1, RB0, RB1);
    // kc = 18
    WAITG(0); __syncthreads();
    mma_chunk<0>(acc, RA0, RA1, RB0, RB1);

    // -------------------- in-register LSTM epilogue -------------------------
    const int u0 = nh + wn * 8 + 2 * q;
    const float2 bi = *(const float2*)(g_bias + 0 * HID + u0);
    const float2 bf = *(const float2*)(g_bias + 1 * HID + u0);
    const float2 bg = *(const float2*)(g_bias + 2 * HID + u0);
    const float2 bo = *(const float2*)(g_bias + 3 * HID + u0);

    #pragma unroll
    for (int m = 0; m < 4; m++) {
        #pragma unroll
        for (int rh = 0; rh < 2; rh++) {
            const int row = brow0 + wm * 64 + m * 16 + g + rh * 8;
            const int s0 = rh * 2;
            float* cptr = g_c  + (size_t)row * HID + u0;
            float* hptr = hout + (size_t)row * HID + u0;
            float2 cv = *(const float2*)(cptr);

            float i0 = sigm (acc[m][0][s0]     + bi.x);
            float f0 = sigm (acc[m][1][s0]     + bf.x);
            float g0 = tanh_(acc[m][2][s0]     + bg.x);
            float o0 = sigm (acc[m][3][s0]     + bo.x);
            float i1 = sigm (acc[m][0][s0 + 1] + bi.y);
            float f1 = sigm (acc[m][1][s0 + 1] + bf.y);
            float g1 = tanh_(acc[m][2][s0 + 1] + bg.y);
            float o1 = sigm (acc[m][3][s0 + 1] + bo.y);

            float cn0 = fmaf(f0, cv.x, i0 * g0);
            float cn1 = fmaf(f1, cv.y, i1 * g1);
            *(float2*)(cptr) = make_float2(cn0, cn1);
            *(float2*)(hptr) = make_float2(to_tf32(o0 * tanh_(cn0)),
                                           to_tf32(o1 * tanh_(cn1)));
        }
    }
}

// ------------------------------- final kernel -------------------------------
__global__ void final_kernel(const float* __restrict__ Wout, const float* __restrict__ bout,
                             float* __restrict__ out) {
    int idx = blockIdx.x * blockDim.x + threadIdx.x;
    if (idx >= BATCH * 10) return;
    int b = idx / 10, cls = idx % 10;
    const float* h  = g_h[0] + (size_t)b * HID;        // step 31 wrote g_h[0]
    const float* wv = Wout + (size_t)cls * HID;
    float acc = 0.f;
    #pragma unroll 4
    for (int i = 0; i < HID; i += 4) {
        float4 hv = *(const float4*)(h + i);
        float4 wf = *(const float4*)(wv + i);
        acc = fmaf(hv.x, wf.x, acc);
        acc = fmaf(hv.y, wf.y, acc);
        acc = fmaf(hv.z, wf.z, acc);
        acc = fmaf(hv.w, wf.w, acc);
    }
    out[idx] = acc + bout[cls];
}

// --------------------------------- launch -----------------------------------
extern "C" void kernel_launch(void* const* d_in, const int* in_sizes, int n_in,
                              void* d_out, int out_size) {
    const float* inputs = (const float*)d_in[0];
    const float* h0     = (const float*)d_in[1];
    const float* c0     = (const float*)d_in[2];
    const float* W_ih   = (const float*)d_in[3];
    const float* W_hh   = (const float*)d_in[4];
    const float* b_ih   = (const float*)d_in[5];
    const float* b_hh   = (const float*)d_in[6];
    const float* W_out  = (const float*)d_in[7];
    const float* b_out  = (const float*)d_in[8];
    float* out = (float*)d_out;
    (void)in_sizes; (void)n_in; (void)out_size;

    cudaFuncSetAttribute(step_kernel, cudaFuncAttributeMaxDynamicSharedMemorySize, SMEM_ALLOC);

    prep_x_kernel<<<(BATCH * 3 * 32 * 32 + 255) / 256, 256>>>(inputs);
    prep_misc_kernel<<<(BATCH * HID + 255) / 256, 256>>>(h0, c0, b_ih, b_hh);
    prep_w_kernel<<<(WT_FLOATS + 255) / 256, 256>>>(W_ih, W_hh);

    dim3 grid(BATCH / 128, HID / 32);   // (64, 16) = 1024 CTAs
    for (int t = 0; t < TSTEPS; t++)
        step_kernel<<<grid, THREADS, SMEM_ALLOC>>>(t);

    final_kernel<<<(BATCH * 10 + 255) / 256, 256>>>(W_out, b_out, out);
}